// round 9
// baseline (speedup 1.0000x reference)
#include <cuda_runtime.h>

// DeltaEncoder: delta -> BatchNorm(1ch eval) -> Linear(1,64) broadcast ->
// LIF recurrence over the 64 output channels. Output [B,O,F,T] f32 (0/1).
// B=32, T=512, F=64, O=64. 268MB output => HBM-write-bound (~6.4TB/s achieved).
// R9 = R8 (block tile (b, 8f, 128t), SMEM-staged input, float4 __stcs stores,
// 1024x256, 8 blocks/SM) + interleaved float2 weights (1 LDS.64 per o) and
// pinned launch bounds.

#define BB 32
#define TT 512
#define FF 64
#define OO 64

__global__ __launch_bounds__(256, 8)
void delta_encoder_kernel(const float* __restrict__ in,     // [B,T,F]
                          const float* __restrict__ enc_w,  // [O]
                          const float* __restrict__ enc_b,  // [O]
                          const float* __restrict__ bn_w,
                          const float* __restrict__ bn_b,
                          const float* __restrict__ bn_mean,
                          const float* __restrict__ bn_var,
                          float* __restrict__ out)          // [B,O,F,T]
{
    // Interleaved (0.5*w, 0.5*b) pairs: h = fmaf(v,0.5, fmaf(x, wb.x, wb.y))
    __shared__ float2 swb[OO];
    // Input tile: rows r=0..128 map to t = t0-1 .. t0+127, 8 f cols, pad to 9
    __shared__ float sx[129 * 9];

    int tid = threadIdx.x;
    if (tid < OO) {
        swb[tid] = make_float2(0.5f * enc_w[tid], 0.5f * enc_b[tid]);
    }

    // Decode block: 1024 blocks = 32 b x 8 f-groups x 4 t-quarters
    int bid = blockIdx.x;
    int b  = bid >> 5;
    int fg = (bid >> 2) & 7;
    int tq = bid & 3;
    int f0 = fg * 8;
    int t0 = tq * 128;

    // Cooperative staged load: 1032 floats, coalesced 32B row-chunks.
    #pragma unroll
    for (int j = tid; j < 129 * 8; j += 256) {
        int r = j >> 3;
        int c = j & 7;
        int t_g = t0 - 1 + r;
        if (t_g < 0) t_g = 0;            // makes delta at t=0 equal 0
        sx[r * 9 + c] = in[(b * TT + t_g) * FF + f0 + c];
    }
    __syncthreads();

    // BatchNorm constants (single channel, eval mode)
    float inv  = bn_w[0] * rsqrtf(bn_var[0] + 1e-5f);
    float mean = bn_mean[0];
    float beta = bn_b[0];

    int wid  = tid >> 5;      // 0..7 -> f = f0 + wid
    int lane = tid & 31;      // 0..31 -> t = t0 + 4*lane
    int f = f0 + wid;
    int t = t0 + lane * 4;

    float xi0 = sx[(lane * 4 + 0) * 9 + wid];
    float xi1 = sx[(lane * 4 + 1) * 9 + wid];
    float xi2 = sx[(lane * 4 + 2) * 9 + wid];
    float xi3 = sx[(lane * 4 + 3) * 9 + wid];
    float xi4 = sx[(lane * 4 + 4) * 9 + wid];

    float x0 = ((xi1 - xi0) - mean) * inv + beta;
    float x1 = ((xi2 - xi1) - mean) * inv + beta;
    float x2 = ((xi3 - xi2) - mean) * inv + beta;
    float x3 = ((xi4 - xi3) - mean) * inv + beta;

    float v0 = 0.f, v1 = 0.f, v2 = 0.f, v3 = 0.f;

    // out[((b*O + o)*F + f)*T + t]; o-stride = F*T*4 bytes = 128KB
    char* op = (char*)(out + ((b * OO) * FF + f) * TT + t);

    #pragma unroll 8
    for (int o = 0; o < OO; o++) {
        float2 wb = swb[o];

        float h0 = fmaf(v0, 0.5f, fmaf(x0, wb.x, wb.y));
        float h1 = fmaf(v1, 0.5f, fmaf(x1, wb.x, wb.y));
        float h2 = fmaf(v2, 0.5f, fmaf(x2, wb.x, wb.y));
        float h3 = fmaf(v3, 0.5f, fmaf(x3, wb.x, wb.y));

        float s0 = (h0 >= 1.0f) ? 1.0f : 0.0f;
        float s1 = (h1 >= 1.0f) ? 1.0f : 0.0f;
        float s2 = (h2 >= 1.0f) ? 1.0f : 0.0f;
        float s3 = (h3 >= 1.0f) ? 1.0f : 0.0f;

        v0 = (h0 >= 1.0f) ? 0.0f : h0;
        v1 = (h1 >= 1.0f) ? 0.0f : h1;
        v2 = (h2 >= 1.0f) ? 0.0f : h2;
        v3 = (h3 >= 1.0f) ? 0.0f : h3;

        __stcs((float4*)op, make_float4(s0, s1, s2, s3));
        op += FF * TT * sizeof(float);   // 128KB per o step
    }
}

extern "C" void kernel_launch(void* const* d_in, const int* in_sizes, int n_in,
                              void* d_out, int out_size) {
    const float* in      = (const float*)d_in[0];
    const float* enc_w   = (const float*)d_in[1];
    const float* enc_b   = (const float*)d_in[2];
    const float* bn_w    = (const float*)d_in[3];
    const float* bn_b    = (const float*)d_in[4];
    const float* bn_mean = (const float*)d_in[5];
    const float* bn_var  = (const float*)d_in[6];
    float* out = (float*)d_out;

    delta_encoder_kernel<<<1024, 256>>>(in, enc_w, enc_b, bn_w, bn_b,
                                        bn_mean, bn_var, out);
}

// round 11
// speedup vs baseline: 1.4572x; 1.4572x over previous
#include <cuda_runtime.h>

// DeltaEncoder: delta -> BatchNorm(1ch eval) -> Linear(1,64) broadcast ->
// LIF recurrence over the 64 output channels. Output [B,O,F,T] f32 (0/1).
// B=32, T=512, F=64, O=64. 268MB output => HBM-write-bound (~6.4TB/s achieved).
// R10 = R8 (SMEM-staged input, float4 __stcs stores via TYPED float4* ptr,
// 1024x256, 4t/thread) with retiled blocks: (b, 2 adjacent f, all 512 t).
// Per o-step each block writes one contiguous 4KB output extent.

#define BB 32
#define TT 512
#define FF 64
#define OO 64

__global__ __launch_bounds__(256)
void delta_encoder_kernel(const float* __restrict__ in,     // [B,T,F]
                          const float* __restrict__ enc_w,  // [O]
                          const float* __restrict__ enc_b,  // [O]
                          const float* __restrict__ bn_w,
                          const float* __restrict__ bn_b,
                          const float* __restrict__ bn_mean,
                          const float* __restrict__ bn_var,
                          float* __restrict__ out)          // [B,O,F,T]
{
    // Weights staged with 1/tau folded: h = fmaf(v,0.5, fmaf(x, 0.5w, 0.5b))
    __shared__ float sw[OO];
    __shared__ float sb[OO];
    // Input tile: rows r=0..512 map to t = -1(clamped) .. 511, 2 f columns
    __shared__ float sx[513 * 2];

    int tid = threadIdx.x;
    if (tid < OO) {
        sw[tid] = 0.5f * enc_w[tid];
        sb[tid] = 0.5f * enc_b[tid];
    }

    // Decode block: 1024 blocks = 32 b x 32 f-pairs
    int bid = blockIdx.x;
    int b  = bid >> 5;
    int fg = bid & 31;
    int f0 = fg * 2;

    // Cooperative staged load: 1026 floats. Consecutive j -> consecutive
    // (r,c) -> 8B contiguous per row; warp-load touches 16 sectors.
    for (int j = tid; j < 513 * 2; j += 256) {
        int r = j >> 1;
        int c = j & 1;
        int t_g = r - 1;
        if (t_g < 0) t_g = 0;            // makes delta at t=0 equal 0
        sx[j] = in[(b * TT + t_g) * FF + f0 + c];
    }
    __syncthreads();

    // BatchNorm constants (single channel, eval mode)
    float inv  = bn_w[0] * rsqrtf(bn_var[0] + 1e-5f);
    float mean = bn_mean[0];
    float beta = bn_b[0];

    int wid  = tid >> 5;      // 0..7
    int lane = tid & 31;      // 0..31
    int fl = wid & 1;         // f = f0 + fl
    int tq = wid >> 1;        // t-quarter 0..3
    int t  = tq * 128 + lane * 4;

    // xi[i] = in[b, t-1+i, f] = sx[(t+i)*2 + fl]  (row t+i maps t_g = t+i-1)
    float xi0 = sx[(t + 0) * 2 + fl];
    float xi1 = sx[(t + 1) * 2 + fl];
    float xi2 = sx[(t + 2) * 2 + fl];
    float xi3 = sx[(t + 3) * 2 + fl];
    float xi4 = sx[(t + 4) * 2 + fl];

    float x0 = ((xi1 - xi0) - mean) * inv + beta;
    float x1 = ((xi2 - xi1) - mean) * inv + beta;
    float x2 = ((xi3 - xi2) - mean) * inv + beta;
    float x3 = ((xi4 - xi3) - mean) * inv + beta;

    float v0 = 0.f, v1 = 0.f, v2 = 0.f, v3 = 0.f;

    // out[((b*O + o)*F + f0+fl)*T + t]; o-stride = F*T floats = 8192 float4
    float4* op = (float4*)(out + ((b * OO) * FF + f0 + fl) * TT + t);
    const int strideO4 = FF * TT / 4;

    #pragma unroll 8
    for (int o = 0; o < OO; o++) {
        float hw = sw[o];
        float hb = sb[o];

        float h0 = fmaf(v0, 0.5f, fmaf(x0, hw, hb));
        float h1 = fmaf(v1, 0.5f, fmaf(x1, hw, hb));
        float h2 = fmaf(v2, 0.5f, fmaf(x2, hw, hb));
        float h3 = fmaf(v3, 0.5f, fmaf(x3, hw, hb));

        float s0 = (h0 >= 1.0f) ? 1.0f : 0.0f;
        float s1 = (h1 >= 1.0f) ? 1.0f : 0.0f;
        float s2 = (h2 >= 1.0f) ? 1.0f : 0.0f;
        float s3 = (h3 >= 1.0f) ? 1.0f : 0.0f;

        v0 = (h0 >= 1.0f) ? 0.0f : h0;
        v1 = (h1 >= 1.0f) ? 0.0f : h1;
        v2 = (h2 >= 1.0f) ? 0.0f : h2;
        v3 = (h3 >= 1.0f) ? 0.0f : h3;

        __stcs(op, make_float4(s0, s1, s2, s3));
        op += strideO4;
    }
}

extern "C" void kernel_launch(void* const* d_in, const int* in_sizes, int n_in,
                              void* d_out, int out_size) {
    const float* in      = (const float*)d_in[0];
    const float* enc_w   = (const float*)d_in[1];
    const float* enc_b   = (const float*)d_in[2];
    const float* bn_w    = (const float*)d_in[3];
    const float* bn_b    = (const float*)d_in[4];
    const float* bn_mean = (const float*)d_in[5];
    const float* bn_var  = (const float*)d_in[6];
    float* out = (float*)d_out;

    delta_encoder_kernel<<<1024, 256>>>(in, enc_w, enc_b, bn_w, bn_b,
                                        bn_mean, bn_var, out);
}

// round 12
// speedup vs baseline: 1.5309x; 1.0506x over previous
#include <cuda_runtime.h>

// DeltaEncoder: delta -> BatchNorm(1ch eval) -> Linear(1,64) broadcast ->
// LIF recurrence over the 64 output channels. Output [B,O,F,T] f32 (0/1).
// B=32, T=512, F=64, O=64. 268MB output => HBM-write-bound (~6.4TB/s achieved).
// R12 = R8 (block tile (b, 8f, 128t), SMEM-staged input, float4 __stcs stores
// via TYPED float4* pointer, 1024x256) + ONE change: interleaved float2
// weights -> single LDS.64 per o-iteration.

#define BB 32
#define TT 512
#define FF 64
#define OO 64

__global__ __launch_bounds__(256)
void delta_encoder_kernel(const float* __restrict__ in,     // [B,T,F]
                          const float* __restrict__ enc_w,  // [O]
                          const float* __restrict__ enc_b,  // [O]
                          const float* __restrict__ bn_w,
                          const float* __restrict__ bn_b,
                          const float* __restrict__ bn_mean,
                          const float* __restrict__ bn_var,
                          float* __restrict__ out)          // [B,O,F,T]
{
    // Interleaved (0.5*w, 0.5*b): h = fmaf(v, 0.5, fmaf(x, wb.x, wb.y))
    __shared__ float2 swb[OO];
    // Input tile: rows r=0..128 map to t = t0-1 .. t0+127, 8 f cols, pad to 9
    __shared__ float sx[129 * 9];

    int tid = threadIdx.x;
    if (tid < OO) {
        swb[tid] = make_float2(0.5f * enc_w[tid], 0.5f * enc_b[tid]);
    }

    // Decode block: 1024 blocks = 32 b x 8 f-groups x 4 t-quarters
    int bid = blockIdx.x;
    int b  = bid >> 5;
    int fg = (bid >> 2) & 7;
    int tq = bid & 3;
    int f0 = fg * 8;
    int t0 = tq * 128;

    // Cooperative staged load: 1032 floats, coalesced 32B row-chunks.
    #pragma unroll
    for (int j = tid; j < 129 * 8; j += 256) {
        int r = j >> 3;
        int c = j & 7;
        int t_g = t0 - 1 + r;
        if (t_g < 0) t_g = 0;            // makes delta at t=0 equal 0
        sx[r * 9 + c] = in[(b * TT + t_g) * FF + f0 + c];
    }
    __syncthreads();

    // BatchNorm constants (single channel, eval mode)
    float inv  = bn_w[0] * rsqrtf(bn_var[0] + 1e-5f);
    float mean = bn_mean[0];
    float beta = bn_b[0];

    int wid  = tid >> 5;      // 0..7 -> f = f0 + wid
    int lane = tid & 31;      // 0..31 -> t = t0 + 4*lane
    int f = f0 + wid;
    int t = t0 + lane * 4;

    float xi0 = sx[(lane * 4 + 0) * 9 + wid];
    float xi1 = sx[(lane * 4 + 1) * 9 + wid];
    float xi2 = sx[(lane * 4 + 2) * 9 + wid];
    float xi3 = sx[(lane * 4 + 3) * 9 + wid];
    float xi4 = sx[(lane * 4 + 4) * 9 + wid];

    float x0 = ((xi1 - xi0) - mean) * inv + beta;
    float x1 = ((xi2 - xi1) - mean) * inv + beta;
    float x2 = ((xi3 - xi2) - mean) * inv + beta;
    float x3 = ((xi4 - xi3) - mean) * inv + beta;

    float v0 = 0.f, v1 = 0.f, v2 = 0.f, v3 = 0.f;

    // out[((b*O + o)*F + f)*T + t]; o-stride = F*T floats = 8192 float4
    float4* op = (float4*)(out + ((b * OO) * FF + f) * TT + t);
    const int strideO4 = FF * TT / 4;

    #pragma unroll 8
    for (int o = 0; o < OO; o++) {
        float2 wb = swb[o];

        float h0 = fmaf(v0, 0.5f, fmaf(x0, wb.x, wb.y));
        float h1 = fmaf(v1, 0.5f, fmaf(x1, wb.x, wb.y));
        float h2 = fmaf(v2, 0.5f, fmaf(x2, wb.x, wb.y));
        float h3 = fmaf(v3, 0.5f, fmaf(x3, wb.x, wb.y));

        float s0 = (h0 >= 1.0f) ? 1.0f : 0.0f;
        float s1 = (h1 >= 1.0f) ? 1.0f : 0.0f;
        float s2 = (h2 >= 1.0f) ? 1.0f : 0.0f;
        float s3 = (h3 >= 1.0f) ? 1.0f : 0.0f;

        v0 = (h0 >= 1.0f) ? 0.0f : h0;
        v1 = (h1 >= 1.0f) ? 0.0f : h1;
        v2 = (h2 >= 1.0f) ? 0.0f : h2;
        v3 = (h3 >= 1.0f) ? 0.0f : h3;

        __stcs(op, make_float4(s0, s1, s2, s3));
        op += strideO4;
    }
}

extern "C" void kernel_launch(void* const* d_in, const int* in_sizes, int n_in,
                              void* d_out, int out_size) {
    const float* in      = (const float*)d_in[0];
    const float* enc_w   = (const float*)d_in[1];
    const float* enc_b   = (const float*)d_in[2];
    const float* bn_w    = (const float*)d_in[3];
    const float* bn_b    = (const float*)d_in[4];
    const float* bn_mean = (const float*)d_in[5];
    const float* bn_var  = (const float*)d_in[6];
    float* out = (float*)d_out;

    delta_encoder_kernel<<<1024, 256>>>(in, enc_w, enc_b, bn_w, bn_b,
                                        bn_mean, bn_var, out);
}